// round 1
// baseline (speedup 1.0000x reference)
#include <cuda_runtime.h>
#include <cuda_bf16.h>

// out = -0.1f * x, elementwise over 16*4096*1024 = 67,108,864 fp32 elements.
// Pure HBM stream: 256 MiB in + 256 MiB out. Vectorized float4, flat index.

__global__ void scale_kernel_v4(const float4* __restrict__ x,
                                float4* __restrict__ out,
                                int n4) {
    int i = blockIdx.x * blockDim.x + threadIdx.x;
    if (i < n4) {
        float4 v = x[i];
        float4 r;
        r.x = -0.1f * v.x;
        r.y = -0.1f * v.y;
        r.z = -0.1f * v.z;
        r.w = -0.1f * v.w;
        out[i] = r;
    }
}

// Scalar tail fallback (not expected to be used for this shape, but keeps the
// kernel correct for any element count).
__global__ void scale_kernel_tail(const float* __restrict__ x,
                                  float* __restrict__ out,
                                  int start, int n) {
    int i = start + blockIdx.x * blockDim.x + threadIdx.x;
    if (i < n) {
        out[i] = -0.1f * x[i];
    }
}

extern "C" void kernel_launch(void* const* d_in, const int* in_sizes, int n_in,
                              void* d_out, int out_size) {
    const float* x = (const float*)d_in[0];
    float* out = (float*)d_out;
    int n = in_sizes[0];

    int n4 = n / 4;
    if (n4 > 0) {
        const int threads = 256;
        int blocks = (n4 + threads - 1) / threads;
        scale_kernel_v4<<<blocks, threads>>>((const float4*)x, (float4*)out, n4);
    }
    int tail_start = n4 * 4;
    int tail = n - tail_start;
    if (tail > 0) {
        scale_kernel_tail<<<1, 256>>>(x, out, tail_start, n);
    }
}

// round 2
// speedup vs baseline: 1.0078x; 1.0078x over previous
#include <cuda_runtime.h>
#include <cuda_bf16.h>

// out = -0.1f * x over 67,108,864 fp32 elements (256 MiB in + 256 MiB out).
// Pure HBM stream. Strategy: 4x float4 per thread (MLP_p1=4), streaming
// cache hints (.cs) to minimize L2 evict churn on single-touch data.

#define ITEMS 4

__global__ void scale_kernel_v4x4(const float4* __restrict__ x,
                                  float4* __restrict__ out,
                                  int n4) {
    // Block-contiguous tile: blockDim.x * ITEMS float4s per block.
    int base = blockIdx.x * (blockDim.x * ITEMS) + threadIdx.x;

    float4 v[ITEMS];
    int idx[ITEMS];
    bool ok[ITEMS];

    // Front-batch all loads (independent -> deep MLP).
    #pragma unroll
    for (int k = 0; k < ITEMS; k++) {
        idx[k] = base + k * blockDim.x;
        ok[k] = idx[k] < n4;
        if (ok[k]) v[k] = __ldcs(&x[idx[k]]);
    }

    #pragma unroll
    for (int k = 0; k < ITEMS; k++) {
        if (ok[k]) {
            float4 r;
            r.x = -0.1f * v[k].x;
            r.y = -0.1f * v[k].y;
            r.z = -0.1f * v[k].z;
            r.w = -0.1f * v[k].w;
            __stcs(&out[idx[k]], r);
        }
    }
}

// Scalar tail fallback for element counts not divisible by 4.
__global__ void scale_kernel_tail(const float* __restrict__ x,
                                  float* __restrict__ out,
                                  int start, int n) {
    int i = start + blockIdx.x * blockDim.x + threadIdx.x;
    if (i < n) {
        out[i] = -0.1f * x[i];
    }
}

extern "C" void kernel_launch(void* const* d_in, const int* in_sizes, int n_in,
                              void* d_out, int out_size) {
    const float* x = (const float*)d_in[0];
    float* out = (float*)d_out;
    int n = in_sizes[0];

    int n4 = n / 4;
    if (n4 > 0) {
        const int threads = 256;
        int per_block = threads * ITEMS;
        int blocks = (n4 + per_block - 1) / per_block;
        scale_kernel_v4x4<<<blocks, threads>>>((const float4*)x, (float4*)out, n4);
    }
    int tail_start = n4 * 4;
    int tail = n - tail_start;
    if (tail > 0) {
        scale_kernel_tail<<<1, 256>>>(x, out, tail_start, n);
    }
}

// round 3
// speedup vs baseline: 1.0082x; 1.0004x over previous
#include <cuda_runtime.h>
#include <cuda_bf16.h>

// out = -0.1f * x over 67,108,864 fp32 elements (256 MiB in + 256 MiB out).
// Pure HBM stream. ITEMS=8 front-batched float4 loads per thread (128 B read
// burst), streaming hints (.cs), and an exact-fit kernel with no bounds
// checks for the common divisible case.

#define ITEMS 8
#define THREADS 256

// Exact-fit: grid covers n4 exactly, no predication.
__global__ void __launch_bounds__(THREADS)
scale_kernel_exact(const float4* __restrict__ x,
                   float4* __restrict__ out) {
    int base = blockIdx.x * (THREADS * ITEMS) + threadIdx.x;

    float4 v[ITEMS];
    #pragma unroll
    for (int k = 0; k < ITEMS; k++) {
        v[k] = __ldcs(&x[base + k * THREADS]);
    }

    #pragma unroll
    for (int k = 0; k < ITEMS; k++) {
        float4 r;
        r.x = -0.1f * v[k].x;
        r.y = -0.1f * v[k].y;
        r.z = -0.1f * v[k].z;
        r.w = -0.1f * v[k].w;
        __stcs(&out[base + k * THREADS], r);
    }
}

// Guarded generic kernel for sizes that don't divide evenly.
__global__ void __launch_bounds__(THREADS)
scale_kernel_guarded(const float4* __restrict__ x,
                     float4* __restrict__ out,
                     int n4) {
    int base = blockIdx.x * (THREADS * ITEMS) + threadIdx.x;
    #pragma unroll
    for (int k = 0; k < ITEMS; k++) {
        int i = base + k * THREADS;
        if (i < n4) {
            float4 v = __ldcs(&x[i]);
            float4 r;
            r.x = -0.1f * v.x;
            r.y = -0.1f * v.y;
            r.z = -0.1f * v.z;
            r.w = -0.1f * v.w;
            __stcs(&out[i], r);
        }
    }
}

// Scalar tail for element counts not divisible by 4.
__global__ void scale_kernel_tail(const float* __restrict__ x,
                                  float* __restrict__ out,
                                  int start, int n) {
    int i = start + blockIdx.x * blockDim.x + threadIdx.x;
    if (i < n) {
        out[i] = -0.1f * x[i];
    }
}

extern "C" void kernel_launch(void* const* d_in, const int* in_sizes, int n_in,
                              void* d_out, int out_size) {
    const float* x = (const float*)d_in[0];
    float* out = (float*)d_out;
    int n = in_sizes[0];

    int n4 = n / 4;
    const int per_block = THREADS * ITEMS;
    if (n4 > 0) {
        if (n4 % per_block == 0) {
            scale_kernel_exact<<<n4 / per_block, THREADS>>>(
                (const float4*)x, (float4*)out);
        } else {
            int blocks = (n4 + per_block - 1) / per_block;
            scale_kernel_guarded<<<blocks, THREADS>>>(
                (const float4*)x, (float4*)out, n4);
        }
    }
    int tail_start = n4 * 4;
    int tail = n - tail_start;
    if (tail > 0) {
        scale_kernel_tail<<<1, 256>>>(x, out, tail_start, n);
    }
}